// round 14
// baseline (speedup 1.0000x reference)
#include <cuda_runtime.h>
#include <cuda_bf16.h>
#include <math.h>

// Problem constants
#define Bc 8
#define Ec 1024
#define Dc 256
#define Hc 16
#define HDc 16
#define Tc (Bc*Ec)          // 8192 tokens
typedef unsigned int u32;

// ---------------- scratch (device globals: allocation-free) ----------------
__device__ float g_x1 [Tc*Dc];
__device__ float g_tmp[2*Tc*Dc];                       // split-K partials
__device__ __nv_bfloat16 g_xh [Tc*Dc],  g_xl [Tc*Dc];
__device__ __nv_bfloat16 g_qh [Tc*Dc],  g_ql [Tc*Dc];
__device__ __nv_bfloat16 g_kh [Tc*Dc],  g_kl [Tc*Dc];
__device__ __nv_bfloat16 g_vt [Tc*Dc];                 // V transposed per-b: [b][dim][key]
__device__ __nv_bfloat16 g_aoh[Tc*Dc],  g_aol[Tc*Dc];
__device__ __nv_bfloat16 g_x1h[Tc*Dc],  g_x1l[Tc*Dc];
__device__ __nv_bfloat16 g_ffh[Tc*4*Dc], g_ffl[Tc*4*Dc];
// weight splits (transposed [N,K]); wqkv = Wq/Wk/Wv stacked [768,256]
__device__ __nv_bfloat16 g_wqkvh[3*Dc*Dc], g_wqkvl[3*Dc*Dc];
__device__ __nv_bfloat16 g_woh[Dc*Dc],    g_wol[Dc*Dc];
__device__ __nv_bfloat16 g_wf1h[Dc*4*Dc], g_wf1l[Dc*4*Dc];
__device__ __nv_bfloat16 g_wf2h[4*Dc*Dc], g_wf2l[4*Dc*Dc];

// ---------------- helpers ----------------
__device__ __forceinline__ u32 bfpair(float lo, float hi) {
    u32 r;
    asm("cvt.rn.bf16x2.f32 %0, %1, %2;" : "=r"(r) : "f"(hi), "f"(lo));
    return r;
}
__device__ __forceinline__ void bf_hilo2(float a, float b, u32& hp, u32& lp) {
    hp = bfpair(a, b);
    float ha = __int_as_float(hp << 16);
    float hb = __int_as_float(hp & 0xffff0000u);
    lp = bfpair(a - ha, b - hb);
}
__device__ __forceinline__ float gelu_exact(float v) {
    return 0.5f * v * (1.0f + erff(v * 0.7071067811865476f));
}
__device__ __forceinline__ void mma16816(
    float& d0, float& d1, float& d2, float& d3,
    u32 a0, u32 a1, u32 a2, u32 a3, u32 b0, u32 b1)
{
    asm("mma.sync.aligned.m16n8k16.row.col.f32.bf16.bf16.f32 "
        "{%0,%1,%2,%3}, {%4,%5,%6,%7}, {%8,%9}, {%0,%1,%2,%3};"
        : "+f"(d0), "+f"(d1), "+f"(d2), "+f"(d3)
        : "r"(a0), "r"(a1), "r"(a2), "r"(a3), "r"(b0), "r"(b1));
}
__device__ __forceinline__ void cpa16(u32 dst, const void* src) {
    asm volatile("cp.async.ca.shared.global [%0], [%1], 16;" :: "r"(dst), "l"(src));
}
__device__ __forceinline__ void cpa8(u32 dst, const void* src) {
    asm volatile("cp.async.ca.shared.global [%0], [%1], 8;" :: "r"(dst), "l"(src));
}

// ---------------- fp32 -> bf16 hi/lo split (x input only) ----------------
__global__ __launch_bounds__(256) void split2_kernel(
    const float* __restrict__ in, __nv_bfloat16* __restrict__ hi,
    __nv_bfloat16* __restrict__ lo, int n4)
{
    int i = blockIdx.x * 256 + threadIdx.x;
    if (i >= n4) return;
    float4 f = ((const float4*)in)[i];
    u32 h0, l0, h1, l1;
    bf_hilo2(f.x, f.y, h0, l0);
    bf_hilo2(f.z, f.w, h1, l1);
    ((uint2*)hi)[i] = make_uint2(h0, h1);
    ((uint2*)lo)[i] = make_uint2(l0, l1);
}

// ---------------- all weight splits: W[K,N] -> hiT/loT[N,K]; QKV stacked ----------------
__global__ __launch_bounds__(256) void splitW_all(
    const float* __restrict__ Wq, const float* __restrict__ Wk,
    const float* __restrict__ Wv, const float* __restrict__ Wo,
    const float* __restrict__ Wf1, const float* __restrict__ Wf2,
    __nv_bfloat16* __restrict__ qkvh, __nv_bfloat16* __restrict__ qkvl,
    __nv_bfloat16* __restrict__ oh, __nv_bfloat16* __restrict__ ol,
    __nv_bfloat16* __restrict__ f1h, __nv_bfloat16* __restrict__ f1l,
    __nv_bfloat16* __restrict__ f2h, __nv_bfloat16* __restrict__ f2l)
{
    int bid = blockIdx.x;
    const float* W;
    __nv_bfloat16 *hiT, *loT;
    int K, N, idx;
    if (bid < 1024) {
        int m = bid >> 8;                    // Wq/Wk/Wv (stacked) or Wo
        K = Dc; N = Dc;
        idx = (bid & 255) * 256 + threadIdx.x;
        if (m < 3) { W = (m == 0) ? Wq : (m == 1) ? Wk : Wv;
                     hiT = qkvh + m * Dc * Dc; loT = qkvl + m * Dc * Dc; }
        else       { W = Wo; hiT = oh; loT = ol; }
    } else if (bid < 2048) {
        K = Dc; N = 4 * Dc;
        idx = (bid - 1024) * 256 + threadIdx.x;
        W = Wf1; hiT = f1h; loT = f1l;
    } else {
        K = 4 * Dc; N = Dc;
        idx = (bid - 2048) * 256 + threadIdx.x;
        W = Wf2; hiT = f2h; loT = f2l;
    }
    int k = idx / N, n = idx - k * N;
    float f = W[idx];
    __nv_bfloat16 h = __float2bfloat16(f);
    float r = f - __bfloat162float(h);
    hiT[(size_t)n * K + k] = h;
    loT[(size_t)n * K + k] = __float2bfloat16(r);
}

// ---------------- tensor-core GEMM, cp.async double-buffered, split-K capable ----------------
// C = A @ B^T + bias; A hi/lo [M,Ktot] bf16, BT hi/lo [N,Ktot] bf16, fp32 accumulate.
// mode 0: fp32 Cf (partial z at Cf + z*M*N). mode 1: bf16 hi/lo (Chi,Clo).
// mode 2: QKV triple output — cols 0-255 -> Chi/Clo (Q), 256-511 -> C2hi/C2lo (K),
//         512-767 -> C3 transposed bf16 [b][dim][tok] (V).
#define SAPITCH 24

__global__ __launch_bounds__(256) void gemm_mma(
    const __nv_bfloat16* __restrict__ Ahi, const __nv_bfloat16* __restrict__ Alo,
    const __nv_bfloat16* __restrict__ BhiT, const __nv_bfloat16* __restrict__ BloT,
    const float* __restrict__ biasA, const float* __restrict__ biasB2,
    const float* __restrict__ biasC,
    float* __restrict__ Cf,
    __nv_bfloat16* __restrict__ Chi, __nv_bfloat16* __restrict__ Clo,
    __nv_bfloat16* __restrict__ C2hi, __nv_bfloat16* __restrict__ C2lo,
    __nv_bfloat16* __restrict__ C3,
    int M, int N, int Ktot, int nsplit, int act, int mode)
{
    __shared__ __align__(16) __nv_bfloat16 sA[2][2][128 * SAPITCH];  // [stage][split]
    __shared__ __align__(16) __nv_bfloat16 sB[2][2][64 * SAPITCH];

    const int tid  = threadIdx.x;
    const int warp = tid >> 5;
    const int lane = tid & 31;
    const int g    = lane >> 2;
    const int tq   = lane & 3;
    const int wm   = (warp >> 1) * 32;
    const int wn   = (warp & 1) * 32;
    const int m0   = blockIdx.y * 128, n0 = blockIdx.x * 64;
    const int Kit  = Ktot / nsplit;
    const int kofs = blockIdx.z * Kit;
    const bool z0  = (blockIdx.z == 0);

    float acc[2][4][4];
    #pragma unroll
    for (int i = 0; i < 2; i++)
        #pragma unroll
        for (int j = 0; j < 4; j++)
            #pragma unroll
            for (int c = 0; c < 4; c++) acc[i][j][c] = 0.0f;

    const int ar = tid >> 1, akh = (tid & 1) * 8;
    const int bn = tid >> 2, bkq = (tid & 3) * 4;

    u32 dA0[2], dA1[2], dB0[2], dB1[2];
    #pragma unroll
    for (int st = 0; st < 2; st++) {
        dA0[st] = (u32)__cvta_generic_to_shared(&sA[st][0][ar * SAPITCH + akh]);
        dA1[st] = (u32)__cvta_generic_to_shared(&sA[st][1][ar * SAPITCH + akh]);
        dB0[st] = (u32)__cvta_generic_to_shared(&sB[st][0][bn * SAPITCH + bkq]);
        dB1[st] = (u32)__cvta_generic_to_shared(&sB[st][1][bn * SAPITCH + bkq]);
    }

    const __nv_bfloat16* Abase = Ahi + (size_t)(m0 + ar) * Ktot + kofs + akh;
    const __nv_bfloat16* Lbase = Alo + (size_t)(m0 + ar) * Ktot + kofs + akh;
    const __nv_bfloat16* Bbase = BhiT + (size_t)(n0 + bn) * Ktot + kofs + bkq;
    const __nv_bfloat16* Wbase = BloT + (size_t)(n0 + bn) * Ktot + kofs + bkq;

    // prologue: prefetch first k-tile into stage 0
    cpa16(dA0[0], Abase);
    cpa16(dA1[0], Lbase);
    cpa8 (dB0[0], Bbase);
    cpa8 (dB1[0], Wbase);
    asm volatile("cp.async.commit_group;");

    int stage = 0;
    for (int k0 = 0; k0 < Kit; k0 += 16) {
        asm volatile("cp.async.wait_group 0;" ::: "memory");
        __syncthreads();
        if (k0 + 16 < Kit) {
            int st = stage ^ 1, kn = k0 + 16;
            cpa16(dA0[st], Abase + kn);
            cpa16(dA1[st], Lbase + kn);
            cpa8 (dB0[st], Bbase + kn);
            cpa8 (dB1[st], Wbase + kn);
            asm volatile("cp.async.commit_group;");
        }

        u32 afr[2][2][4];
        #pragma unroll
        for (int s = 0; s < 2; s++)
            #pragma unroll
            for (int mt = 0; mt < 2; mt++) {
                int r = wm + mt * 16 + g;
                afr[s][mt][0] = *(const u32*)&sA[stage][s][(r    ) * SAPITCH + tq * 2    ];
                afr[s][mt][1] = *(const u32*)&sA[stage][s][(r + 8) * SAPITCH + tq * 2    ];
                afr[s][mt][2] = *(const u32*)&sA[stage][s][(r    ) * SAPITCH + tq * 2 + 8];
                afr[s][mt][3] = *(const u32*)&sA[stage][s][(r + 8) * SAPITCH + tq * 2 + 8];
            }
        u32 bfr[2][4][2];
        #pragma unroll
        for (int s = 0; s < 2; s++)
            #pragma unroll
            for (int nt = 0; nt < 4; nt++) {
                int r = wn + nt * 8 + g;
                bfr[s][nt][0] = *(const u32*)&sB[stage][s][r * SAPITCH + tq * 2    ];
                bfr[s][nt][1] = *(const u32*)&sB[stage][s][r * SAPITCH + tq * 2 + 8];
            }

        #pragma unroll
        for (int mt = 0; mt < 2; mt++)
            #pragma unroll
            for (int nt = 0; nt < 4; nt++) {
                float* d = acc[mt][nt];
                mma16816(d[0], d[1], d[2], d[3],
                         afr[0][mt][0], afr[0][mt][1], afr[0][mt][2], afr[0][mt][3],
                         bfr[0][nt][0], bfr[0][nt][1]);
                mma16816(d[0], d[1], d[2], d[3],
                         afr[0][mt][0], afr[0][mt][1], afr[0][mt][2], afr[0][mt][3],
                         bfr[1][nt][0], bfr[1][nt][1]);
                mma16816(d[0], d[1], d[2], d[3],
                         afr[1][mt][0], afr[1][mt][1], afr[1][mt][2], afr[1][mt][3],
                         bfr[0][nt][0], bfr[0][nt][1]);
            }
        stage ^= 1;
    }

    #pragma unroll
    for (int mt = 0; mt < 2; mt++) {
        int rowA = m0 + wm + mt * 16 + g;
        #pragma unroll
        for (int nt = 0; nt < 4; nt++) {
            int col = n0 + wn + nt * 8 + tq * 2;
            float* d = acc[mt][nt];
            if (mode == 2) {
                int sel = col >> 8;
                int c   = col & 255;
                const float* bsel = (sel == 0) ? biasA : (sel == 1) ? biasB2 : biasC;
                float b0 = bsel[c], b1 = bsel[c + 1];
                float o0 = d[0] + b0, o1 = d[1] + b1;
                float o2 = d[2] + b0, o3 = d[3] + b1;
                if (sel == 0) {
                    u32 hp, lp;
                    bf_hilo2(o0, o1, hp, lp);
                    *(u32*)(Chi + (size_t)rowA * Dc + c) = hp;
                    *(u32*)(Clo + (size_t)rowA * Dc + c) = lp;
                    bf_hilo2(o2, o3, hp, lp);
                    *(u32*)(Chi + (size_t)(rowA + 8) * Dc + c) = hp;
                    *(u32*)(Clo + (size_t)(rowA + 8) * Dc + c) = lp;
                } else if (sel == 1) {
                    u32 hp, lp;
                    bf_hilo2(o0, o1, hp, lp);
                    *(u32*)(C2hi + (size_t)rowA * Dc + c) = hp;
                    *(u32*)(C2lo + (size_t)rowA * Dc + c) = lp;
                    bf_hilo2(o2, o3, hp, lp);
                    *(u32*)(C2hi + (size_t)(rowA + 8) * Dc + c) = hp;
                    *(u32*)(C2lo + (size_t)(rowA + 8) * Dc + c) = lp;
                } else {
                    // V transposed: vt[b][dim][tok]
                    int bb = rowA >> 10, t = rowA & 1023;
                    __nv_bfloat16* p0 = C3 + ((size_t)bb * Dc + c) * Ec + t;
                    __nv_bfloat16* p1 = C3 + ((size_t)bb * Dc + c + 1) * Ec + t;
                    p0[0] = __float2bfloat16(o0);
                    p1[0] = __float2bfloat16(o1);
                    p0[8] = __float2bfloat16(o2);
                    p1[8] = __float2bfloat16(o3);
                }
            } else {
                float b0 = 0.0f, b1 = 0.0f;
                if (z0) { b0 = biasA[col]; b1 = biasA[col + 1]; }
                float o0 = d[0] + b0, o1 = d[1] + b1;
                float o2 = d[2] + b0, o3 = d[3] + b1;
                if (act) {
                    o0 = gelu_exact(o0); o1 = gelu_exact(o1);
                    o2 = gelu_exact(o2); o3 = gelu_exact(o3);
                }
                if (mode == 0) {
                    float* Cz = Cf + (size_t)blockIdx.z * M * N;
                    *(float2*)(Cz + (size_t)rowA * N + col)       = make_float2(o0, o1);
                    *(float2*)(Cz + (size_t)(rowA + 8) * N + col) = make_float2(o2, o3);
                } else {
                    u32 hp, lp;
                    bf_hilo2(o0, o1, hp, lp);
                    *(u32*)(Chi + (size_t)rowA * N + col) = hp;
                    *(u32*)(Clo + (size_t)rowA * N + col) = lp;
                    bf_hilo2(o2, o3, hp, lp);
                    *(u32*)(Chi + (size_t)(rowA + 8) * N + col) = hp;
                    *(u32*)(Clo + (size_t)(rowA + 8) * N + col) = lp;
                }
            }
        }
    }
}

// ---------------- tensor-core attention: 32 q/block, 32 keys/tile ----------------
#define KP 136   // sK row pitch (bf16): 128 dims + 8 pad
#define VP 40    // sVt row pitch (bf16): 32 keys + 8 pad

__global__ __launch_bounds__(256, 2) void attn_mma(
    const __nv_bfloat16* __restrict__ Qh, const __nv_bfloat16* __restrict__ Ql,
    const __nv_bfloat16* __restrict__ Kh, const __nv_bfloat16* __restrict__ Kl,
    const __nv_bfloat16* __restrict__ Vt,
    const int* __restrict__ sbias, const unsigned char* __restrict__ mask,
    const float* __restrict__ bias_emb,
    __nv_bfloat16* __restrict__ Ohi, __nv_bfloat16* __restrict__ Olo)
{
    __shared__ __align__(16) __nv_bfloat16 sKh[32 * KP];
    __shared__ __align__(16) __nv_bfloat16 sKl[32 * KP];
    __shared__ __align__(16) __nv_bfloat16 sVt[128 * VP];
    __shared__ int   sSB[32 * 33];
    __shared__ float sBE[8 * 8];
    __shared__ float sM[32];

    const int b    = blockIdx.y;
    const int q0   = blockIdx.x * 32;
    const int hg   = blockIdx.z;
    const int tid  = threadIdx.x;
    const int wid  = tid >> 5;
    const int lane = tid & 31;
    const int g    = lane >> 2;
    const int tq   = lane & 3;
    const int head = hg * 8 + wid;

    if (tid < 48) {
        int idx = tid >> 3, hh = tid & 7;
        sBE[hh * 8 + idx] = bias_emb[idx * Hc + hg * 8 + hh];
    }

    // Q fragments: 2 q-tiles x (hi,lo) x 4 regs
    u32 aQh[2][4], aQl[2][4];
    #pragma unroll
    for (int qt = 0; qt < 2; qt++) {
        const __nv_bfloat16* q0p = Qh + ((size_t)(b * Ec + q0 + qt * 16 + g)) * Dc + head * HDc;
        const __nv_bfloat16* q8p = q0p + (size_t)8 * Dc;
        aQh[qt][0] = *(const u32*)(q0p + tq * 2);
        aQh[qt][1] = *(const u32*)(q8p + tq * 2);
        aQh[qt][2] = *(const u32*)(q0p + tq * 2 + 8);
        aQh[qt][3] = *(const u32*)(q8p + tq * 2 + 8);
        const __nv_bfloat16* l0p = Ql + ((size_t)(b * Ec + q0 + qt * 16 + g)) * Dc + head * HDc;
        const __nv_bfloat16* l8p = l0p + (size_t)8 * Dc;
        aQl[qt][0] = *(const u32*)(l0p + tq * 2);
        aQl[qt][1] = *(const u32*)(l8p + tq * 2);
        aQl[qt][2] = *(const u32*)(l0p + tq * 2 + 8);
        aQl[qt][3] = *(const u32*)(l8p + tq * 2 + 8);
    }

    float oacc[2][2][4];
    #pragma unroll
    for (int qt = 0; qt < 2; qt++)
        #pragma unroll
        for (int n = 0; n < 2; n++)
            #pragma unroll
            for (int e = 0; e < 4; e++) oacc[qt][n][e] = 0.0f;
    float lsum[2][2] = {};

    const int kr  = tid >> 4,  kc8 = (tid & 15) * 8;    // K tile
    const int vd  = tid >> 2,  vk8 = (tid & 3) * 8;     // Vt tile
    const int sbr = tid >> 3,  sbc = (tid & 7) * 4;     // SB tile

    for (int k0 = 0; k0 < Ec; k0 += 32) {
        __syncthreads();
        {
            const __nv_bfloat16* Kg = Kh + ((size_t)(b * Ec + k0)) * Dc + hg * 128;
            const __nv_bfloat16* Lg = Kl + ((size_t)(b * Ec + k0)) * Dc + hg * 128;
            *(uint4*)&sKh[kr * KP + kc8]        = *(const uint4*)(Kg + (size_t)kr * Dc + kc8);
            *(uint4*)&sKh[(kr + 16) * KP + kc8] = *(const uint4*)(Kg + (size_t)(kr + 16) * Dc + kc8);
            *(uint4*)&sKl[kr * KP + kc8]        = *(const uint4*)(Lg + (size_t)kr * Dc + kc8);
            *(uint4*)&sKl[(kr + 16) * KP + kc8] = *(const uint4*)(Lg + (size_t)(kr + 16) * Dc + kc8);
            const __nv_bfloat16* Vg = Vt + ((size_t)b * Dc + hg * 128) * Ec + k0;
            *(uint4*)&sVt[vd * VP + vk8]        = *(const uint4*)(Vg + (size_t)vd * Ec + vk8);
            *(uint4*)&sVt[(vd + 64) * VP + vk8] = *(const uint4*)(Vg + (size_t)(vd + 64) * Ec + vk8);
            int4 t = *(const int4*)(sbias + (size_t)b * Ec * Ec + (size_t)(q0 + sbr) * Ec + k0 + sbc);
            int* d = &sSB[sbr * 33 + sbc];
            d[0] = t.x; d[1] = t.y; d[2] = t.z; d[3] = t.w;
            if (tid < 32) sM[tid] = mask[b * Ec + k0 + tid] ? -1e30f : 0.0f;
        }
        __syncthreads();

        // ---- scores: 2 q-tiles x 4 key-tiles, hi/lo split (3 mma) ----
        float c[2][4][4];
        #pragma unroll
        for (int nt = 0; nt < 4; nt++) {
            int krow = (nt * 8 + g) * KP + wid * HDc;
            u32 bh0 = *(const u32*)&sKh[krow + tq * 2];
            u32 bh1 = *(const u32*)&sKh[krow + tq * 2 + 8];
            u32 bl0 = *(const u32*)&sKl[krow + tq * 2];
            u32 bl1 = *(const u32*)&sKl[krow + tq * 2 + 8];
            #pragma unroll
            for (int qt = 0; qt < 2; qt++) {
                float* d = c[qt][nt];
                d[0] = d[1] = d[2] = d[3] = 0.0f;
                mma16816(d[0], d[1], d[2], d[3],
                         aQh[qt][0], aQh[qt][1], aQh[qt][2], aQh[qt][3], bh0, bh1);
                mma16816(d[0], d[1], d[2], d[3],
                         aQh[qt][0], aQh[qt][1], aQh[qt][2], aQh[qt][3], bl0, bl1);
                mma16816(d[0], d[1], d[2], d[3],
                         aQl[qt][0], aQl[qt][1], aQl[qt][2], aQl[qt][3], bh0, bh1);
            }
        }

        // ---- softmax + PV per q-tile ----
        #pragma unroll
        for (int qt = 0; qt < 2; qt++) {
            const int* sr0 = &sSB[(qt * 16 + g) * 33];
            const int* sr8 = &sSB[(qt * 16 + g + 8) * 33];
            const float* be = &sBE[wid * 8];
            float p[4][4];
            #pragma unroll
            for (int nt = 0; nt < 4; nt++) {
                int kc = nt * 8 + tq * 2;
                float m0v = sM[kc], m1v = sM[kc + 1];
                float e0 = __expf(fmaf(c[qt][nt][0], 0.25f, be[sr0[kc]]     + m0v));
                float e1 = __expf(fmaf(c[qt][nt][1], 0.25f, be[sr0[kc + 1]] + m1v));
                float e2 = __expf(fmaf(c[qt][nt][2], 0.25f, be[sr8[kc]]     + m0v));
                float e3 = __expf(fmaf(c[qt][nt][3], 0.25f, be[sr8[kc + 1]] + m1v));
                lsum[qt][0] += e0 + e1;
                lsum[qt][1] += e2 + e3;
                p[nt][0] = e0; p[nt][1] = e1; p[nt][2] = e2; p[nt][3] = e3;
            }
            u32 pa[2][4];
            #pragma unroll
            for (int ch = 0; ch < 2; ch++) {
                pa[ch][0] = bfpair(p[2*ch][0],   p[2*ch][1]);
                pa[ch][1] = bfpair(p[2*ch][2],   p[2*ch][3]);
                pa[ch][2] = bfpair(p[2*ch+1][0], p[2*ch+1][1]);
                pa[ch][3] = bfpair(p[2*ch+1][2], p[2*ch+1][3]);
            }
            #pragma unroll
            for (int n = 0; n < 2; n++) {
                int vrow = (wid * HDc + n * 8 + g) * VP;
                #pragma unroll
                for (int ch = 0; ch < 2; ch++) {
                    u32 bv0 = *(const u32*)&sVt[vrow + ch * 16 + tq * 2];
                    u32 bv1 = *(const u32*)&sVt[vrow + ch * 16 + tq * 2 + 8];
                    mma16816(oacc[qt][n][0], oacc[qt][n][1], oacc[qt][n][2], oacc[qt][n][3],
                             pa[ch][0], pa[ch][1], pa[ch][2], pa[ch][3], bv0, bv1);
                }
            }
        }
    }

    #pragma unroll
    for (int qt = 0; qt < 2; qt++) {
        float l0 = lsum[qt][0], l1 = lsum[qt][1];
        l0 += __shfl_xor_sync(0xFFFFFFFFu, l0, 1);
        l0 += __shfl_xor_sync(0xFFFFFFFFu, l0, 2);
        l1 += __shfl_xor_sync(0xFFFFFFFFu, l1, 1);
        l1 += __shfl_xor_sync(0xFFFFFFFFu, l1, 2);
        float i0 = 1.0f / l0, i1 = 1.0f / l1;
        #pragma unroll
        for (int n = 0; n < 2; n++) {
            size_t r0 = ((size_t)(b * Ec + q0 + qt * 16 + g)) * Dc + head * HDc + n * 8 + tq * 2;
            size_t r8 = r0 + (size_t)8 * Dc;
            u32 hp, lp;
            bf_hilo2(oacc[qt][n][0] * i0, oacc[qt][n][1] * i0, hp, lp);
            *(u32*)(Ohi + r0) = hp;
            *(u32*)(Olo + r0) = lp;
            bf_hilo2(oacc[qt][n][2] * i1, oacc[qt][n][3] * i1, hp, lp);
            *(u32*)(Ohi + r8) = hp;
            *(u32*)(Olo + r8) = lp;
        }
    }
}

// ---------------- residual add (x + y0 + y1) + layernorm (+ optional bf16 hi/lo) ----------------
__global__ __launch_bounds__(256) void add_ln_kernel(
    const float* __restrict__ x, const float* __restrict__ y0,
    const float* __restrict__ y1,
    const float* __restrict__ g, const float* __restrict__ b,
    float* __restrict__ out,
    __nv_bfloat16* __restrict__ ohi, __nv_bfloat16* __restrict__ olo)
{
    const int row  = blockIdx.x * 8 + (threadIdx.x >> 5);
    const int lane = threadIdx.x & 31;
    const float* xr  = x  + (size_t)row * Dc;
    const float* y0r = y0 + (size_t)row * Dc;
    const float* y1r = y1 + (size_t)row * Dc;

    float v[8];
    float s = 0.0f, s2 = 0.0f;
    #pragma unroll
    for (int i = 0; i < 8; i++) {
        int c = i * 32 + lane;
        float t = xr[c] + y0r[c] + y1r[c];
        v[i] = t;
        s += t;
        s2 = fmaf(t, t, s2);
    }
    #pragma unroll
    for (int o = 16; o > 0; o >>= 1) {
        s  += __shfl_xor_sync(0xFFFFFFFFu, s,  o);
        s2 += __shfl_xor_sync(0xFFFFFFFFu, s2, o);
    }
    float mu  = s * (1.0f / 256.0f);
    float var = s2 * (1.0f / 256.0f) - mu * mu;
    float r   = rsqrtf(var + 1e-5f);
    #pragma unroll
    for (int i = 0; i < 8; i++) {
        int c = i * 32 + lane;
        float o = (v[i] - mu) * r * g[c] + b[c];
        out[(size_t)row * Dc + c] = o;
        if (ohi) {
            __nv_bfloat16 h = __float2bfloat16(o);
            ohi[(size_t)row * Dc + c] = h;
            olo[(size_t)row * Dc + c] = __float2bfloat16(o - __bfloat162float(h));
        }
    }
}

// ---------------- launch ----------------
extern "C" void kernel_launch(void* const* d_in, const int* in_sizes, int n_in,
                              void* d_out, int out_size)
{
    const float* x    = (const float*)d_in[0];
    const int*   sb   = (const int*)d_in[1];
    const unsigned char* mask = (const unsigned char*)d_in[2];
    const float* Wq = (const float*)d_in[3];  const float* bq = (const float*)d_in[4];
    const float* Wk = (const float*)d_in[5];  const float* bk = (const float*)d_in[6];
    const float* Wv = (const float*)d_in[7];  const float* bv = (const float*)d_in[8];
    const float* Wo = (const float*)d_in[9];  const float* bo = (const float*)d_in[10];
    const float* be = (const float*)d_in[11];
    const float* g1 = (const float*)d_in[12]; const float* b1 = (const float*)d_in[13];
    const float* Wf1 = (const float*)d_in[14]; const float* bf1 = (const float*)d_in[15];
    const float* Wf2 = (const float*)d_in[16]; const float* bf2 = (const float*)d_in[17];
    const float* g2 = (const float*)d_in[18]; const float* b2 = (const float*)d_in[19];
    float* out = (float*)d_out;

    float *x1, *tmp;
    __nv_bfloat16 *xh, *xl, *qh, *ql, *kh, *kl, *vt, *aoh, *aol, *x1h, *x1l, *ffh, *ffl;
    __nv_bfloat16 *wqkvh, *wqkvl, *woh, *wol, *wf1h, *wf1l, *wf2h, *wf2l;
    cudaGetSymbolAddress((void**)&x1,  g_x1);
    cudaGetSymbolAddress((void**)&tmp, g_tmp);
    cudaGetSymbolAddress((void**)&xh,  g_xh);  cudaGetSymbolAddress((void**)&xl,  g_xl);
    cudaGetSymbolAddress((void**)&qh,  g_qh);  cudaGetSymbolAddress((void**)&ql,  g_ql);
    cudaGetSymbolAddress((void**)&kh,  g_kh);  cudaGetSymbolAddress((void**)&kl,  g_kl);
    cudaGetSymbolAddress((void**)&vt,  g_vt);
    cudaGetSymbolAddress((void**)&aoh, g_aoh); cudaGetSymbolAddress((void**)&aol, g_aol);
    cudaGetSymbolAddress((void**)&x1h, g_x1h); cudaGetSymbolAddress((void**)&x1l, g_x1l);
    cudaGetSymbolAddress((void**)&ffh, g_ffh); cudaGetSymbolAddress((void**)&ffl, g_ffl);
    cudaGetSymbolAddress((void**)&wqkvh, g_wqkvh); cudaGetSymbolAddress((void**)&wqkvl, g_wqkvl);
    cudaGetSymbolAddress((void**)&woh, g_woh); cudaGetSymbolAddress((void**)&wol, g_wol);
    cudaGetSymbolAddress((void**)&wf1h, g_wf1h); cudaGetSymbolAddress((void**)&wf1l, g_wf1l);
    cudaGetSymbolAddress((void**)&wf2h, g_wf2h); cudaGetSymbolAddress((void**)&wf2l, g_wf2l);

    const int nX = Tc * Dc;
    float* tmp1 = tmp + (size_t)Tc * Dc;

    split2_kernel<<<nX / 4 / 256, 256>>>(x, xh, xl, nX / 4);
    splitW_all<<<3072, 256>>>(Wq, Wk, Wv, Wo, Wf1, Wf2,
                              wqkvh, wqkvl, woh, wol, wf1h, wf1l, wf2h, wf2l);

    // fused QKV projection: N=768, 768 CTAs; Q->qh/ql, K->kh/kl, V->vt (transposed)
    gemm_mma<<<dim3(12, 64, 1), 256>>>(xh, xl, wqkvh, wqkvl, bq, bk, bv,
                                       nullptr, qh, ql, kh, kl, vt,
                                       Tc, 3 * Dc, Dc, 1, 0, 2);

    attn_mma<<<dim3(Ec / 32, Bc, 2), 256>>>(qh, ql, kh, kl, vt, sb, mask, be, aoh, aol);

    // O projection, split-K x2 -> partials tmp[0], tmp[1]
    gemm_mma<<<dim3(4, 64, 2), 256>>>(aoh, aol, woh, wol, bo, nullptr, nullptr,
                                      tmp, nullptr, nullptr, nullptr, nullptr, nullptr,
                                      Tc, Dc, Dc, 2, 0, 0);
    add_ln_kernel<<<Tc / 8, 256>>>(x, tmp, tmp1, g1, b1, x1, x1h, x1l);

    // FFN
    gemm_mma<<<dim3(16, 64, 1), 256>>>(x1h, x1l, wf1h, wf1l, bf1, nullptr, nullptr,
                                       nullptr, ffh, ffl, nullptr, nullptr, nullptr,
                                       Tc, 4 * Dc, Dc, 1, 1, 1);
    gemm_mma<<<dim3(4, 64, 2), 256>>>(ffh, ffl, wf2h, wf2l, bf2, nullptr, nullptr,
                                      tmp, nullptr, nullptr, nullptr, nullptr, nullptr,
                                      Tc, Dc, 4 * Dc, 2, 0, 0);
    add_ln_kernel<<<Tc / 8, 256>>>(x1, tmp, tmp1, g2, b2, out, nullptr, nullptr);
}

// round 16
// speedup vs baseline: 1.7006x; 1.7006x over previous
#include <cuda_runtime.h>
#include <cuda_bf16.h>
#include <math.h>

// Problem constants
#define Bc 8
#define Ec 1024
#define Dc 256
#define Hc 16
#define HDc 16
#define Tc (Bc*Ec)          // 8192 tokens
typedef unsigned int u32;

// ---------------- scratch (device globals: allocation-free) ----------------
__device__ float g_x1 [Tc*Dc];
__device__ float g_tmp[Tc*Dc];
__device__ __nv_bfloat16 g_xh [Tc*Dc],  g_xl [Tc*Dc];
__device__ __nv_bfloat16 g_qh [Tc*Dc],  g_ql [Tc*Dc];
__device__ __nv_bfloat16 g_kh [Tc*Dc],  g_kl [Tc*Dc];
__device__ __nv_bfloat16 g_vt [Tc*Dc];                 // V transposed per-b: [b][dim][key]
__device__ __nv_bfloat16 g_aoh[Tc*Dc],  g_aol[Tc*Dc];
__device__ __nv_bfloat16 g_x1h[Tc*Dc],  g_x1l[Tc*Dc];
__device__ __nv_bfloat16 g_ffh[Tc*4*Dc], g_ffl[Tc*4*Dc];
// per-weight splits (transposed [N,K])
__device__ __nv_bfloat16 g_wqh[Dc*Dc],   g_wql[Dc*Dc];
__device__ __nv_bfloat16 g_wkh[Dc*Dc],   g_wkl[Dc*Dc];
__device__ __nv_bfloat16 g_wvh[Dc*Dc],   g_wvl[Dc*Dc];
__device__ __nv_bfloat16 g_woh[Dc*Dc],   g_wol[Dc*Dc];
__device__ __nv_bfloat16 g_wf1h[Dc*4*Dc], g_wf1l[Dc*4*Dc];
__device__ __nv_bfloat16 g_wf2h[4*Dc*Dc], g_wf2l[4*Dc*Dc];

// ---------------- helpers ----------------
__device__ __forceinline__ u32 bfpair(float lo, float hi) {
    u32 r;
    asm("cvt.rn.bf16x2.f32 %0, %1, %2;" : "=r"(r) : "f"(hi), "f"(lo));
    return r;
}
__device__ __forceinline__ void bf_hilo2(float a, float b, u32& hp, u32& lp) {
    hp = bfpair(a, b);
    float ha = __int_as_float(hp << 16);
    float hb = __int_as_float(hp & 0xffff0000u);
    lp = bfpair(a - ha, b - hb);
}
__device__ __forceinline__ float gelu_exact(float v) {
    return 0.5f * v * (1.0f + erff(v * 0.7071067811865476f));
}
__device__ __forceinline__ void mma16816(
    float& d0, float& d1, float& d2, float& d3,
    u32 a0, u32 a1, u32 a2, u32 a3, u32 b0, u32 b1)
{
    asm("mma.sync.aligned.m16n8k16.row.col.f32.bf16.bf16.f32 "
        "{%0,%1,%2,%3}, {%4,%5,%6,%7}, {%8,%9}, {%0,%1,%2,%3};"
        : "+f"(d0), "+f"(d1), "+f"(d2), "+f"(d3)
        : "r"(a0), "r"(a1), "r"(a2), "r"(a3), "r"(b0), "r"(b1));
}
__device__ __forceinline__ void cpa16(u32 dst, const void* src) {
    asm volatile("cp.async.ca.shared.global [%0], [%1], 16;" :: "r"(dst), "l"(src));
}
__device__ __forceinline__ void cpa8(u32 dst, const void* src) {
    asm volatile("cp.async.ca.shared.global [%0], [%1], 8;" :: "r"(dst), "l"(src));
}

// ---------------- fp32 -> bf16 hi/lo split (x input only) ----------------
__global__ __launch_bounds__(256) void split2_kernel(
    const float* __restrict__ in, __nv_bfloat16* __restrict__ hi,
    __nv_bfloat16* __restrict__ lo, int n4)
{
    int i = blockIdx.x * 256 + threadIdx.x;
    if (i >= n4) return;
    float4 f = ((const float4*)in)[i];
    u32 h0, l0, h1, l1;
    bf_hilo2(f.x, f.y, h0, l0);
    bf_hilo2(f.z, f.w, h1, l1);
    ((uint2*)hi)[i] = make_uint2(h0, h1);
    ((uint2*)lo)[i] = make_uint2(l0, l1);
}

// ---------------- all weight splits (one kernel): W[K,N] -> hiT/loT[N,K] ----------------
__global__ __launch_bounds__(256) void splitW_all(
    const float* __restrict__ Wq, const float* __restrict__ Wk,
    const float* __restrict__ Wv, const float* __restrict__ Wo,
    const float* __restrict__ Wf1, const float* __restrict__ Wf2,
    __nv_bfloat16* __restrict__ qh, __nv_bfloat16* __restrict__ ql,
    __nv_bfloat16* __restrict__ kh, __nv_bfloat16* __restrict__ kl,
    __nv_bfloat16* __restrict__ vh, __nv_bfloat16* __restrict__ vl,
    __nv_bfloat16* __restrict__ oh, __nv_bfloat16* __restrict__ ol,
    __nv_bfloat16* __restrict__ f1h, __nv_bfloat16* __restrict__ f1l,
    __nv_bfloat16* __restrict__ f2h, __nv_bfloat16* __restrict__ f2l)
{
    int bid = blockIdx.x;
    const float* W;
    __nv_bfloat16 *hiT, *loT;
    int K, N, idx;
    if (bid < 1024) {
        int m = bid >> 8;                    // which of Wq/Wk/Wv/Wo
        K = Dc; N = Dc;
        idx = (bid & 255) * 256 + threadIdx.x;
        if      (m == 0) { W = Wq; hiT = qh; loT = ql; }
        else if (m == 1) { W = Wk; hiT = kh; loT = kl; }
        else if (m == 2) { W = Wv; hiT = vh; loT = vl; }
        else             { W = Wo; hiT = oh; loT = ol; }
    } else if (bid < 2048) {
        K = Dc; N = 4 * Dc;
        idx = (bid - 1024) * 256 + threadIdx.x;
        W = Wf1; hiT = f1h; loT = f1l;
    } else {
        K = 4 * Dc; N = Dc;
        idx = (bid - 2048) * 256 + threadIdx.x;
        W = Wf2; hiT = f2h; loT = f2l;
    }
    int k = idx / N, n = idx - k * N;
    float f = W[idx];
    __nv_bfloat16 h = __float2bfloat16(f);
    float r = f - __bfloat162float(h);
    hiT[(size_t)n * K + k] = h;
    loT[(size_t)n * K + k] = __float2bfloat16(r);
}

// ---------------- tensor-core GEMM, cp.async double-buffered (round-11 proven) ----------------
// C = A @ B^T + bias; A hi/lo [M,K] bf16, BT hi/lo [N,K] bf16, fp32 accumulate.
// mode 0: fp32 C.  mode 1: bf16 hi/lo C.  mode 2: bf16 Vt [b][row][tok].
#define SAPITCH 24

__global__ __launch_bounds__(256) void gemm_mma(
    const __nv_bfloat16* __restrict__ Ahi, const __nv_bfloat16* __restrict__ Alo,
    const __nv_bfloat16* __restrict__ BhiT, const __nv_bfloat16* __restrict__ BloT,
    const float* __restrict__ bias,
    float* __restrict__ Cf, __nv_bfloat16* __restrict__ Chi, __nv_bfloat16* __restrict__ Clo,
    int M, int N, int K, int act, int mode, int biasrow)
{
    __shared__ __align__(16) __nv_bfloat16 sA[2][2][128 * SAPITCH];  // [stage][split]
    __shared__ __align__(16) __nv_bfloat16 sB[2][2][64 * SAPITCH];

    const int tid  = threadIdx.x;
    const int warp = tid >> 5;
    const int lane = tid & 31;
    const int g    = lane >> 2;
    const int tq   = lane & 3;
    const int wm   = (warp >> 1) * 32;
    const int wn   = (warp & 1) * 32;
    const int m0   = blockIdx.y * 128, n0 = blockIdx.x * 64;

    float acc[2][4][4];
    #pragma unroll
    for (int i = 0; i < 2; i++)
        #pragma unroll
        for (int j = 0; j < 4; j++)
            #pragma unroll
            for (int c = 0; c < 4; c++) acc[i][j][c] = 0.0f;

    const int ar = tid >> 1, akh = (tid & 1) * 8;
    const int bn = tid >> 2, bkq = (tid & 3) * 4;

    u32 dA0[2], dA1[2], dB0[2], dB1[2];
    #pragma unroll
    for (int st = 0; st < 2; st++) {
        dA0[st] = (u32)__cvta_generic_to_shared(&sA[st][0][ar * SAPITCH + akh]);
        dA1[st] = (u32)__cvta_generic_to_shared(&sA[st][1][ar * SAPITCH + akh]);
        dB0[st] = (u32)__cvta_generic_to_shared(&sB[st][0][bn * SAPITCH + bkq]);
        dB1[st] = (u32)__cvta_generic_to_shared(&sB[st][1][bn * SAPITCH + bkq]);
    }

    // prologue: prefetch k0 = 0 into stage 0
    cpa16(dA0[0], Ahi + (size_t)(m0 + ar) * K + akh);
    cpa16(dA1[0], Alo + (size_t)(m0 + ar) * K + akh);
    cpa8 (dB0[0], BhiT + (size_t)(n0 + bn) * K + bkq);
    cpa8 (dB1[0], BloT + (size_t)(n0 + bn) * K + bkq);
    asm volatile("cp.async.commit_group;");

    int stage = 0;
    for (int k0 = 0; k0 < K; k0 += 16) {
        asm volatile("cp.async.wait_group 0;" ::: "memory");
        __syncthreads();
        if (k0 + 16 < K) {
            int st = stage ^ 1, kn = k0 + 16;
            cpa16(dA0[st], Ahi + (size_t)(m0 + ar) * K + kn + akh);
            cpa16(dA1[st], Alo + (size_t)(m0 + ar) * K + kn + akh);
            cpa8 (dB0[st], BhiT + (size_t)(n0 + bn) * K + kn + bkq);
            cpa8 (dB1[st], BloT + (size_t)(n0 + bn) * K + kn + bkq);
            asm volatile("cp.async.commit_group;");
        }

        u32 afr[2][2][4];
        #pragma unroll
        for (int s = 0; s < 2; s++)
            #pragma unroll
            for (int mt = 0; mt < 2; mt++) {
                int r = wm + mt * 16 + g;
                afr[s][mt][0] = *(const u32*)&sA[stage][s][(r    ) * SAPITCH + tq * 2    ];
                afr[s][mt][1] = *(const u32*)&sA[stage][s][(r + 8) * SAPITCH + tq * 2    ];
                afr[s][mt][2] = *(const u32*)&sA[stage][s][(r    ) * SAPITCH + tq * 2 + 8];
                afr[s][mt][3] = *(const u32*)&sA[stage][s][(r + 8) * SAPITCH + tq * 2 + 8];
            }
        u32 bfr[2][4][2];
        #pragma unroll
        for (int s = 0; s < 2; s++)
            #pragma unroll
            for (int nt = 0; nt < 4; nt++) {
                int r = wn + nt * 8 + g;
                bfr[s][nt][0] = *(const u32*)&sB[stage][s][r * SAPITCH + tq * 2    ];
                bfr[s][nt][1] = *(const u32*)&sB[stage][s][r * SAPITCH + tq * 2 + 8];
            }

        #pragma unroll
        for (int mt = 0; mt < 2; mt++)
            #pragma unroll
            for (int nt = 0; nt < 4; nt++) {
                float* d = acc[mt][nt];
                mma16816(d[0], d[1], d[2], d[3],
                         afr[0][mt][0], afr[0][mt][1], afr[0][mt][2], afr[0][mt][3],
                         bfr[0][nt][0], bfr[0][nt][1]);
                mma16816(d[0], d[1], d[2], d[3],
                         afr[0][mt][0], afr[0][mt][1], afr[0][mt][2], afr[0][mt][3],
                         bfr[1][nt][0], bfr[1][nt][1]);
                mma16816(d[0], d[1], d[2], d[3],
                         afr[1][mt][0], afr[1][mt][1], afr[1][mt][2], afr[1][mt][3],
                         bfr[0][nt][0], bfr[0][nt][1]);
            }
        stage ^= 1;
    }

    #pragma unroll
    for (int mt = 0; mt < 2; mt++) {
        int rowA = m0 + wm + mt * 16 + g;
        #pragma unroll
        for (int nt = 0; nt < 4; nt++) {
            int col = n0 + wn + nt * 8 + tq * 2;
            float b0, b1, b2, b3;
            if (biasrow) {
                b0 = b1 = bias[rowA];
                b2 = b3 = bias[rowA + 8];
            } else {
                b0 = b2 = bias[col];
                b1 = b3 = bias[col + 1];
            }
            float* d = acc[mt][nt];
            float o0 = d[0] + b0, o1 = d[1] + b1;
            float o2 = d[2] + b2, o3 = d[3] + b3;
            if (act) {
                o0 = gelu_exact(o0); o1 = gelu_exact(o1);
                o2 = gelu_exact(o2); o3 = gelu_exact(o3);
            }
            if (mode == 0) {
                *(float2*)(Cf + (size_t)rowA * N + col)       = make_float2(o0, o1);
                *(float2*)(Cf + (size_t)(rowA + 8) * N + col) = make_float2(o2, o3);
            } else if (mode == 1) {
                u32 hp, lp;
                bf_hilo2(o0, o1, hp, lp);
                *(u32*)(Chi + (size_t)rowA * N + col) = hp;
                *(u32*)(Clo + (size_t)rowA * N + col) = lp;
                bf_hilo2(o2, o3, hp, lp);
                *(u32*)(Chi + (size_t)(rowA + 8) * N + col) = hp;
                *(u32*)(Clo + (size_t)(rowA + 8) * N + col) = lp;
            } else {
                int bb = col >> 10, tc = col & 1023;
                *(u32*)(Chi + ((size_t)bb * Dc + rowA) * Ec + tc)     = bfpair(o0, o1);
                *(u32*)(Chi + ((size_t)bb * Dc + rowA + 8) * Ec + tc) = bfpair(o2, o3);
            }
        }
    }
}

// ---------------- tensor-core attention: cp.async double-buffered, 2-term QK ----------------
#define KP 136   // sK row pitch (bf16): 272B = 17*16 (cp.async-aligned)
#define VP 40    // sVt row pitch (bf16): 80B = 5*16 (cp.async-aligned)
#define SP 36    // sSB row pitch (ints): 144B = 9*16 (cp.async-aligned)

__global__ __launch_bounds__(256, 2) void attn_mma(
    const __nv_bfloat16* __restrict__ Qh, const __nv_bfloat16* __restrict__ Ql,
    const __nv_bfloat16* __restrict__ Kh,
    const __nv_bfloat16* __restrict__ Vt,
    const int* __restrict__ sbias, const unsigned char* __restrict__ mask,
    const float* __restrict__ bias_emb,
    __nv_bfloat16* __restrict__ Ohi, __nv_bfloat16* __restrict__ Olo)
{
    __shared__ __align__(16) __nv_bfloat16 sKh[2][32 * KP];
    __shared__ __align__(16) __nv_bfloat16 sVt[2][128 * VP];
    __shared__ __align__(16) int  sSB[2][32 * SP];
    __shared__ __align__(16) unsigned char sMb[2][32];
    __shared__ float sBE[8 * 8];

    const int b    = blockIdx.y;
    const int q0   = blockIdx.x * 32;
    const int hg   = blockIdx.z;
    const int tid  = threadIdx.x;
    const int wid  = tid >> 5;
    const int lane = tid & 31;
    const int g    = lane >> 2;
    const int tq   = lane & 3;
    const int head = hg * 8 + wid;

    if (tid < 48) {
        int idx = tid >> 3, hh = tid & 7;
        sBE[hh * 8 + idx] = bias_emb[idx * Hc + hg * 8 + hh];
    }

    // Q fragments: 2 q-tiles x (hi,lo) x 4 regs
    u32 aQh[2][4], aQl[2][4];
    #pragma unroll
    for (int qt = 0; qt < 2; qt++) {
        const __nv_bfloat16* q0p = Qh + ((size_t)(b * Ec + q0 + qt * 16 + g)) * Dc + head * HDc;
        const __nv_bfloat16* q8p = q0p + (size_t)8 * Dc;
        aQh[qt][0] = *(const u32*)(q0p + tq * 2);
        aQh[qt][1] = *(const u32*)(q8p + tq * 2);
        aQh[qt][2] = *(const u32*)(q0p + tq * 2 + 8);
        aQh[qt][3] = *(const u32*)(q8p + tq * 2 + 8);
        const __nv_bfloat16* l0p = Ql + ((size_t)(b * Ec + q0 + qt * 16 + g)) * Dc + head * HDc;
        const __nv_bfloat16* l8p = l0p + (size_t)8 * Dc;
        aQl[qt][0] = *(const u32*)(l0p + tq * 2);
        aQl[qt][1] = *(const u32*)(l8p + tq * 2);
        aQl[qt][2] = *(const u32*)(l0p + tq * 2 + 8);
        aQl[qt][3] = *(const u32*)(l8p + tq * 2 + 8);
    }

    float oacc[2][2][4];
    #pragma unroll
    for (int qt = 0; qt < 2; qt++)
        #pragma unroll
        for (int n = 0; n < 2; n++)
            #pragma unroll
            for (int e = 0; e < 4; e++) oacc[qt][n][e] = 0.0f;
    float lsum[2][2] = {};

    const int kr  = tid >> 4,  kc8 = (tid & 15) * 8;    // K tile cover
    const int vd  = tid >> 2,  vk8 = (tid & 3) * 8;     // Vt tile cover
    const int sbr = tid >> 3,  sbc = (tid & 7) * 4;     // SB tile cover

    u32 dK[2], dK2[2], dV[2], dV2[2], dS[2], dM[2];
    #pragma unroll
    for (int st = 0; st < 2; st++) {
        dK[st]  = (u32)__cvta_generic_to_shared(&sKh[st][kr * KP + kc8]);
        dK2[st] = (u32)__cvta_generic_to_shared(&sKh[st][(kr + 16) * KP + kc8]);
        dV[st]  = (u32)__cvta_generic_to_shared(&sVt[st][vd * VP + vk8]);
        dV2[st] = (u32)__cvta_generic_to_shared(&sVt[st][(vd + 64) * VP + vk8]);
        dS[st]  = (u32)__cvta_generic_to_shared(&sSB[st][sbr * SP + sbc]);
        dM[st]  = (u32)__cvta_generic_to_shared(&sMb[st][(tid & 1) * 16]);
    }
    const __nv_bfloat16* Kgb = Kh + ((size_t)(b * Ec)) * Dc + hg * 128;
    const __nv_bfloat16* Vgb = Vt + ((size_t)b * Dc + hg * 128) * Ec;
    const int* SBb = sbias + (size_t)b * Ec * Ec + (size_t)q0 * Ec;
    const unsigned char* Mb = mask + b * Ec;

    // prologue: prefetch tile 0 into stage 0
    {
        cpa16(dK[0],  Kgb + (size_t)kr * Dc + kc8);
        cpa16(dK2[0], Kgb + (size_t)(kr + 16) * Dc + kc8);
        cpa16(dV[0],  Vgb + (size_t)vd * Ec + vk8);
        cpa16(dV2[0], Vgb + (size_t)(vd + 64) * Ec + vk8);
        cpa16(dS[0],  SBb + (size_t)sbr * Ec + sbc);
        if (tid < 2) cpa16(dM[0], Mb + tid * 16);
        asm volatile("cp.async.commit_group;");
    }

    int stage = 0;
    for (int k0 = 0; k0 < Ec; k0 += 32) {
        asm volatile("cp.async.wait_group 0;" ::: "memory");
        __syncthreads();
        if (k0 + 32 < Ec) {
            int st = stage ^ 1, kn = k0 + 32;
            cpa16(dK[st],  Kgb + (size_t)(kn + kr) * Dc + kc8);
            cpa16(dK2[st], Kgb + (size_t)(kn + kr + 16) * Dc + kc8);
            cpa16(dV[st],  Vgb + (size_t)vd * Ec + kn + vk8);
            cpa16(dV2[st], Vgb + (size_t)(vd + 64) * Ec + kn + vk8);
            cpa16(dS[st],  SBb + (size_t)sbr * Ec + kn + sbc);
            if (tid < 2) cpa16(dM[st], Mb + kn + tid * 16);
            asm volatile("cp.async.commit_group;");
        }

        // ---- scores: 2 q-tiles x 4 key-tiles, 2-term QK (hh + lh) ----
        float c[2][4][4];
        #pragma unroll
        for (int nt = 0; nt < 4; nt++) {
            int krow = (nt * 8 + g) * KP + wid * HDc;
            u32 bh0 = *(const u32*)&sKh[stage][krow + tq * 2];
            u32 bh1 = *(const u32*)&sKh[stage][krow + tq * 2 + 8];
            #pragma unroll
            for (int qt = 0; qt < 2; qt++) {
                float* d = c[qt][nt];
                d[0] = d[1] = d[2] = d[3] = 0.0f;
                mma16816(d[0], d[1], d[2], d[3],
                         aQh[qt][0], aQh[qt][1], aQh[qt][2], aQh[qt][3], bh0, bh1);
                mma16816(d[0], d[1], d[2], d[3],
                         aQl[qt][0], aQl[qt][1], aQl[qt][2], aQl[qt][3], bh0, bh1);
            }
        }

        // ---- softmax + PV per q-tile ----
        #pragma unroll
        for (int qt = 0; qt < 2; qt++) {
            const int* sr0 = &sSB[stage][(qt * 16 + g) * SP];
            const int* sr8 = &sSB[stage][(qt * 16 + g + 8) * SP];
            const float* be = &sBE[wid * 8];
            const unsigned char* mb = sMb[stage];
            float p[4][4];
            #pragma unroll
            for (int nt = 0; nt < 4; nt++) {
                int kc = nt * 8 + tq * 2;
                float m0v = mb[kc]     ? -1e30f : 0.0f;
                float m1v = mb[kc + 1] ? -1e30f : 0.0f;
                float e0 = __expf(fmaf(c[qt][nt][0], 0.25f, be[sr0[kc]]     + m0v));
                float e1 = __expf(fmaf(c[qt][nt][1], 0.25f, be[sr0[kc + 1]] + m1v));
                float e2 = __expf(fmaf(c[qt][nt][2], 0.25f, be[sr8[kc]]     + m0v));
                float e3 = __expf(fmaf(c[qt][nt][3], 0.25f, be[sr8[kc + 1]] + m1v));
                lsum[qt][0] += e0 + e1;
                lsum[qt][1] += e2 + e3;
                p[nt][0] = e0; p[nt][1] = e1; p[nt][2] = e2; p[nt][3] = e3;
            }
            u32 pa[2][4];
            #pragma unroll
            for (int ch = 0; ch < 2; ch++) {
                pa[ch][0] = bfpair(p[2*ch][0],   p[2*ch][1]);
                pa[ch][1] = bfpair(p[2*ch][2],   p[2*ch][3]);
                pa[ch][2] = bfpair(p[2*ch+1][0], p[2*ch+1][1]);
                pa[ch][3] = bfpair(p[2*ch+1][2], p[2*ch+1][3]);
            }
            #pragma unroll
            for (int n = 0; n < 2; n++) {
                int vrow = (wid * HDc + n * 8 + g) * VP;
                #pragma unroll
                for (int ch = 0; ch < 2; ch++) {
                    u32 bv0 = *(const u32*)&sVt[stage][vrow + ch * 16 + tq * 2];
                    u32 bv1 = *(const u32*)&sVt[stage][vrow + ch * 16 + tq * 2 + 8];
                    mma16816(oacc[qt][n][0], oacc[qt][n][1], oacc[qt][n][2], oacc[qt][n][3],
                             pa[ch][0], pa[ch][1], pa[ch][2], pa[ch][3], bv0, bv1);
                }
            }
        }
        stage ^= 1;
    }

    #pragma unroll
    for (int qt = 0; qt < 2; qt++) {
        float l0 = lsum[qt][0], l1 = lsum[qt][1];
        l0 += __shfl_xor_sync(0xFFFFFFFFu, l0, 1);
        l0 += __shfl_xor_sync(0xFFFFFFFFu, l0, 2);
        l1 += __shfl_xor_sync(0xFFFFFFFFu, l1, 1);
        l1 += __shfl_xor_sync(0xFFFFFFFFu, l1, 2);
        float i0 = 1.0f / l0, i1 = 1.0f / l1;
        #pragma unroll
        for (int n = 0; n < 2; n++) {
            size_t r0 = ((size_t)(b * Ec + q0 + qt * 16 + g)) * Dc + head * HDc + n * 8 + tq * 2;
            size_t r8 = r0 + (size_t)8 * Dc;
            u32 hp, lp;
            bf_hilo2(oacc[qt][n][0] * i0, oacc[qt][n][1] * i0, hp, lp);
            *(u32*)(Ohi + r0) = hp;
            *(u32*)(Olo + r0) = lp;
            bf_hilo2(oacc[qt][n][2] * i1, oacc[qt][n][3] * i1, hp, lp);
            *(u32*)(Ohi + r8) = hp;
            *(u32*)(Olo + r8) = lp;
        }
    }
}

// ---------------- residual add + layernorm (+ optional bf16 hi/lo out) ----------------
__global__ __launch_bounds__(256) void add_ln_kernel(
    const float* __restrict__ x, const float* __restrict__ y,
    const float* __restrict__ g, const float* __restrict__ b,
    float* __restrict__ out,
    __nv_bfloat16* __restrict__ ohi, __nv_bfloat16* __restrict__ olo)
{
    const int row  = blockIdx.x * 8 + (threadIdx.x >> 5);
    const int lane = threadIdx.x & 31;
    const float* xr = x + (size_t)row * Dc;
    const float* yr = y + (size_t)row * Dc;

    float v[8];
    float s = 0.0f, s2 = 0.0f;
    #pragma unroll
    for (int i = 0; i < 8; i++) {
        float t = xr[i * 32 + lane] + yr[i * 32 + lane];
        v[i] = t;
        s += t;
        s2 = fmaf(t, t, s2);
    }
    #pragma unroll
    for (int o = 16; o > 0; o >>= 1) {
        s  += __shfl_xor_sync(0xFFFFFFFFu, s,  o);
        s2 += __shfl_xor_sync(0xFFFFFFFFu, s2, o);
    }
    float mu  = s * (1.0f / 256.0f);
    float var = s2 * (1.0f / 256.0f) - mu * mu;
    float r   = rsqrtf(var + 1e-5f);
    #pragma unroll
    for (int i = 0; i < 8; i++) {
        int c = i * 32 + lane;
        float o = (v[i] - mu) * r * g[c] + b[c];
        out[(size_t)row * Dc + c] = o;
        if (ohi) {
            __nv_bfloat16 h = __float2bfloat16(o);
            ohi[(size_t)row * Dc + c] = h;
            olo[(size_t)row * Dc + c] = __float2bfloat16(o - __bfloat162float(h));
        }
    }
}

// ---------------- launch ----------------
extern "C" void kernel_launch(void* const* d_in, const int* in_sizes, int n_in,
                              void* d_out, int out_size)
{
    const float* x    = (const float*)d_in[0];
    const int*   sb   = (const int*)d_in[1];
    const unsigned char* mask = (const unsigned char*)d_in[2];
    const float* Wq = (const float*)d_in[3];  const float* bq = (const float*)d_in[4];
    const float* Wk = (const float*)d_in[5];  const float* bk = (const float*)d_in[6];
    const float* Wv = (const float*)d_in[7];  const float* bv = (const float*)d_in[8];
    const float* Wo = (const float*)d_in[9];  const float* bo = (const float*)d_in[10];
    const float* be = (const float*)d_in[11];
    const float* g1 = (const float*)d_in[12]; const float* b1 = (const float*)d_in[13];
    const float* Wf1 = (const float*)d_in[14]; const float* bf1 = (const float*)d_in[15];
    const float* Wf2 = (const float*)d_in[16]; const float* bf2 = (const float*)d_in[17];
    const float* g2 = (const float*)d_in[18]; const float* b2 = (const float*)d_in[19];
    float* out = (float*)d_out;

    float *x1, *tmp;
    __nv_bfloat16 *xh, *xl, *qh, *ql, *kh, *kl, *vt, *aoh, *aol, *x1h, *x1l, *ffh, *ffl;
    __nv_bfloat16 *wqh, *wql, *wkh, *wkl, *wvh, *wvl, *woh, *wol, *wf1h, *wf1l, *wf2h, *wf2l;
    cudaGetSymbolAddress((void**)&x1,  g_x1);
    cudaGetSymbolAddress((void**)&tmp, g_tmp);
    cudaGetSymbolAddress((void**)&xh,  g_xh);  cudaGetSymbolAddress((void**)&xl,  g_xl);
    cudaGetSymbolAddress((void**)&qh,  g_qh);  cudaGetSymbolAddress((void**)&ql,  g_ql);
    cudaGetSymbolAddress((void**)&kh,  g_kh);  cudaGetSymbolAddress((void**)&kl,  g_kl);
    cudaGetSymbolAddress((void**)&vt,  g_vt);
    cudaGetSymbolAddress((void**)&aoh, g_aoh); cudaGetSymbolAddress((void**)&aol, g_aol);
    cudaGetSymbolAddress((void**)&x1h, g_x1h); cudaGetSymbolAddress((void**)&x1l, g_x1l);
    cudaGetSymbolAddress((void**)&ffh, g_ffh); cudaGetSymbolAddress((void**)&ffl, g_ffl);
    cudaGetSymbolAddress((void**)&wqh, g_wqh); cudaGetSymbolAddress((void**)&wql, g_wql);
    cudaGetSymbolAddress((void**)&wkh, g_wkh); cudaGetSymbolAddress((void**)&wkl, g_wkl);
    cudaGetSymbolAddress((void**)&wvh, g_wvh); cudaGetSymbolAddress((void**)&wvl, g_wvl);
    cudaGetSymbolAddress((void**)&woh, g_woh); cudaGetSymbolAddress((void**)&wol, g_wol);
    cudaGetSymbolAddress((void**)&wf1h, g_wf1h); cudaGetSymbolAddress((void**)&wf1l, g_wf1l);
    cudaGetSymbolAddress((void**)&wf2h, g_wf2h); cudaGetSymbolAddress((void**)&wf2l, g_wf2l);

    const int nX = Tc * Dc;
    dim3 gD (Dc / 64,     Tc / 128);   // (4, 64)
    dim3 gF1(4 * Dc / 64, Tc / 128);   // (16, 64)
    dim3 gVt(Tc / 64,     Dc / 128);   // (128, 2)

    split2_kernel<<<nX / 4 / 256, 256>>>(x, xh, xl, nX / 4);
    splitW_all<<<3072, 256>>>(Wq, Wk, Wv, Wo, Wf1, Wf2,
                              wqh, wql, wkh, wkl, wvh, wvl,
                              woh, wol, wf1h, wf1l, wf2h, wf2l);

    gemm_mma<<<gD, 256>>>(xh, xl, wqh, wql, bq, nullptr, qh, ql, Tc, Dc, Dc, 0, 1, 0);
    gemm_mma<<<gD, 256>>>(xh, xl, wkh, wkl, bk, nullptr, kh, kl, Tc, Dc, Dc, 0, 1, 0);
    gemm_mma<<<gVt, 256>>>(wvh, wvl, xh, xl, bv, nullptr, vt, nullptr, Dc, Tc, Dc, 0, 2, 1);

    attn_mma<<<dim3(Ec / 32, Bc, 2), 256>>>(qh, ql, kh, vt, sb, mask, be, aoh, aol);

    gemm_mma<<<gD, 256>>>(aoh, aol, woh, wol, bo, tmp, nullptr, nullptr, Tc, Dc, Dc, 0, 0, 0);
    add_ln_kernel<<<Tc / 8, 256>>>(x, tmp, g1, b1, x1, x1h, x1l);

    gemm_mma<<<gF1, 256>>>(x1h, x1l, wf1h, wf1l, bf1, nullptr, ffh, ffl, Tc, 4 * Dc, Dc, 1, 1, 0);
    gemm_mma<<<gD, 256>>>(ffh, ffl, wf2h, wf2l, bf2, tmp, nullptr, nullptr, Tc, Dc, 4 * Dc, 0, 0, 0);
    add_ln_kernel<<<Tc / 8, 256>>>(x1, tmp, g2, b2, out, nullptr, nullptr);
}